// round 4
// baseline (speedup 1.0000x reference)
#include <cuda_runtime.h>

#define BATCH 4096
#define FEAT 40960
#define H1 256
#define CAP 256   // max nonzeros buffered per row (actual data has <=30)

// Scratch (no allocation allowed)
__device__ __align__(128) float g_ftw_t[(size_t)FEAT * H1];  // 42 MB, [feature][h]
__device__ __align__(128) float g_x[(size_t)BATCH * 2 * H1]; // 8 MB,  [row][512]

// Streaming 32B load (evict-first): 8 floats + bitwise nonzero flag.
struct U8 { unsigned long long a, b, c, d; };
__device__ __forceinline__ U8 ld_stream_32B(const float* p) {
    U8 r;
    asm volatile("ld.global.cs.v4.b64 {%0,%1,%2,%3}, [%4];"
                 : "=l"(r.a), "=l"(r.b), "=l"(r.c), "=l"(r.d) : "l"(p));
    return r;
}
__device__ __forceinline__ float u8_get(const U8& r, int j) {
    unsigned long long w = (j < 2) ? r.a : (j < 4) ? r.b : (j < 6) ? r.c : r.d;
    return __uint_as_float((j & 1) ? (unsigned)(w >> 32) : (unsigned)w);
}

// Table gather: 32B load with L2 evict_last (sticky).
struct F8 { float f[8]; };
__device__ __forceinline__ F8 ld_table_f8(const float* p) {
    unsigned long long a, b, c, d;
    asm volatile("ld.global.nc.L2::evict_last.v4.b64 {%0,%1,%2,%3}, [%4];"
                 : "=l"(a), "=l"(b), "=l"(c), "=l"(d) : "l"(p));
    F8 r;
    r.f[0] = __uint_as_float((unsigned)a); r.f[1] = __uint_as_float((unsigned)(a >> 32));
    r.f[2] = __uint_as_float((unsigned)b); r.f[3] = __uint_as_float((unsigned)(b >> 32));
    r.f[4] = __uint_as_float((unsigned)c); r.f[5] = __uint_as_float((unsigned)(c >> 32));
    r.f[6] = __uint_as_float((unsigned)d); r.f[7] = __uint_as_float((unsigned)(d >> 32));
    return r;
}

// ---------------------------------------------------------------------------
// Kernel 1: transpose ft_w [256, 40960] -> g_ftw_t [40960, 256]
// Vectorized: blockDim (8,32); each thread moves one float4 each direction.
// ---------------------------------------------------------------------------
__global__ void __launch_bounds__(256) transpose_kernel(const float* __restrict__ ft_w) {
    __shared__ float tile[32][33];
    int j0 = blockIdx.x * 32;   // feature tile
    int h0 = blockIdx.y * 32;   // hidden tile
    int tx = threadIdx.x;       // 0..7 (float4 across columns)
    int ty = threadIdx.y;       // 0..31

    const float4* src = (const float4*)&ft_w[(size_t)(h0 + ty) * FEAT + j0 + 4 * tx];
    float4 v = *src;
    tile[4 * tx + 0][ty] = v.x;
    tile[4 * tx + 1][ty] = v.y;
    tile[4 * tx + 2][ty] = v.z;
    tile[4 * tx + 3][ty] = v.w;
    __syncthreads();

    float4 o;
    o.x = tile[ty][4 * tx + 0];
    o.y = tile[ty][4 * tx + 1];
    o.z = tile[ty][4 * tx + 2];
    o.w = tile[ty][4 * tx + 3];
    *(float4*)&g_ftw_t[(size_t)(j0 + ty) * H1 + h0 + 4 * tx] = o;
}

// ---------------------------------------------------------------------------
// Kernel 2: per (row, side): streaming 32B scan with one bitwise zero-test per
// chunk -> nonzero extraction -> warp-parallel gather (32B/lane, evict_last)
// -> cross-warp reduction -> bias + crelu -> g_x.
// One block (256 threads = 8 warps) per (row, side).
// ---------------------------------------------------------------------------
__global__ void __launch_bounds__(256) ft_kernel(
    const float* __restrict__ wf, const float* __restrict__ bf,
    const float* __restrict__ ft_b)
{
    __shared__ int   s_idx[CAP];
    __shared__ float s_val[CAP];
    __shared__ int   s_count;
    __shared__ float s_red[8][256];   // per-warp partial sums (8 KB)

    int row  = blockIdx.x;
    int side = blockIdx.y;
    const float* feats = side ? bf : wf;
    const float* frow = feats + (size_t)row * FEAT;
    int tid  = threadIdx.x;
    int warp = tid >> 5, lane = tid & 31;

    if (tid == 0) s_count = 0;
    __syncthreads();

    // 40960 floats / 8 per chunk / 256 threads = 20 iterations.
#pragma unroll 4
    for (int i = tid; i < FEAT / 8; i += 256) {
        U8 r = ld_stream_32B(frow + 8 * i);
        if ((r.a | r.b | r.c | r.d) != 0ull) {   // rare path (~30/5120 chunks)
            int base = 8 * i;
#pragma unroll
            for (int j = 0; j < 8; j++) {
                float f = u8_get(r, j);
                if (f != 0.f) {
                    int p = atomicAdd(&s_count, 1);
                    if (p < CAP) { s_idx[p] = base + j; s_val[p] = f; }
                }
            }
        }
    }
    __syncthreads();

    int n = min(s_count, CAP);

    // Warp w handles nonzeros k = w, w+8, ... Lane accumulates h = lane*8..+7.
    float acc[8];
#pragma unroll
    for (int j = 0; j < 8; j++) acc[j] = 0.f;

    for (int k = warp; k < n; k += 8) {
        float v = s_val[k];
        F8 t = ld_table_f8(&g_ftw_t[(size_t)s_idx[k] * H1 + lane * 8]);
#pragma unroll
        for (int j = 0; j < 8; j++) acc[j] = fmaf(v, t.f[j], acc[j]);
    }

#pragma unroll
    for (int j = 0; j < 8; j++) s_red[warp][lane * 8 + j] = acc[j];
    __syncthreads();

    float r = ft_b[tid];
#pragma unroll
    for (int w = 0; w < 8; w++) r += s_red[w][tid];
    r = fminf(fmaxf(r, 0.f), 1.f);
    g_x[(size_t)row * 512 + side * 256 + tid] = r;
}

// ---------------------------------------------------------------------------
// Kernel 3: tail MLP. One warp per batch row, 8 rows per 256-thread block.
// ---------------------------------------------------------------------------
__global__ void __launch_bounds__(256) mlp_kernel(
    const float* __restrict__ fc1_w, const float* __restrict__ fc1_b,
    const float* __restrict__ fc2_w, const float* __restrict__ fc2_b,
    const float* __restrict__ fc3_w, const float* __restrict__ fc3_b,
    float* __restrict__ out)
{
    __shared__ float fc2t[32 * 32];   // transposed: [j][h]
    __shared__ float s_fc3[32];
    int tid = threadIdx.x;

    for (int i = tid; i < 1024; i += 256) {
        int h = i >> 5, j = i & 31;
        fc2t[j * 32 + h] = fc2_w[i];
    }
    if (tid < 32) s_fc3[tid] = fc3_w[tid];
    __syncthreads();

    int warp = tid >> 5, lane = tid & 31;
    int row = blockIdx.x * 8 + warp;

    const float* xr = g_x + (size_t)row * 512;
    float xv[16];
#pragma unroll
    for (int k = 0; k < 16; k++) xv[k] = xr[lane + 32 * k];

    float y1 = 0.f;
#pragma unroll
    for (int h = 0; h < 32; h++) {
        const float* w = fc1_w + h * 512;
        float p = 0.f;
#pragma unroll
        for (int k = 0; k < 16; k++) p = fmaf(__ldg(&w[lane + 32 * k]), xv[k], p);
#pragma unroll
        for (int o = 16; o; o >>= 1) p += __shfl_xor_sync(0xffffffffu, p, o);
        p += fc1_b[h];
        p = fminf(fmaxf(p, 0.f), 1.f);
        if (lane == h) y1 = p;
    }

    float y2 = fc2_b[lane];
#pragma unroll
    for (int j = 0; j < 32; j++) {
        float xj = __shfl_sync(0xffffffffu, y1, j);
        y2 = fmaf(fc2t[j * 32 + lane], xj, y2);
    }
    y2 = fminf(fmaxf(y2, 0.f), 1.f);

    float p3 = s_fc3[lane] * y2;
#pragma unroll
    for (int o = 16; o; o >>= 1) p3 += __shfl_xor_sync(0xffffffffu, p3, o);
    if (lane == 0) out[row] = p3 + fc3_b[0];
}

// ---------------------------------------------------------------------------
extern "C" void kernel_launch(void* const* d_in, const int* in_sizes, int n_in,
                              void* d_out, int out_size) {
    const float* wf    = (const float*)d_in[0];
    const float* bf    = (const float*)d_in[1];
    const float* ft_w  = (const float*)d_in[2];
    const float* ft_b  = (const float*)d_in[3];
    const float* fc1_w = (const float*)d_in[4];
    const float* fc1_b = (const float*)d_in[5];
    const float* fc2_w = (const float*)d_in[6];
    const float* fc2_b = (const float*)d_in[7];
    const float* fc3_w = (const float*)d_in[8];
    const float* fc3_b = (const float*)d_in[9];
    float* out = (float*)d_out;

    dim3 tb(8, 32);
    dim3 tg(FEAT / 32, H1 / 32);
    transpose_kernel<<<tg, tb>>>(ft_w);

    dim3 fg(BATCH, 2);
    ft_kernel<<<fg, 256>>>(wf, bf, ft_b);

    mlp_kernel<<<BATCH / 8, 256>>>(fc1_w, fc1_b, fc2_w, fc2_b, fc3_w, fc3_b, out);
}

// round 5
// speedup vs baseline: 1.0168x; 1.0168x over previous
#include <cuda_runtime.h>

#define BATCH 4096
#define FEAT 40960
#define H1 256
#define CAP 256        // max nonzeros buffered per row (actual data has <=30)
#define FT_BLOCKS 1184 // 148 SMs * 8 resident blocks: exactly one wave

// Scratch (no allocation allowed)
__device__ __align__(128) float g_ftw_t[(size_t)FEAT * H1];  // 42 MB, [feature][h]
__device__ __align__(128) float g_x[(size_t)BATCH * 2 * H1]; // 8 MB,  [row][512]

// Streaming float4 load: evict-first (don't displace the table in L2)
__device__ __forceinline__ float4 ld_stream_f4(const float4* p) {
    float4 v;
    asm volatile("ld.global.cs.v4.f32 {%0,%1,%2,%3}, [%4];"
                 : "=f"(v.x), "=f"(v.y), "=f"(v.z), "=f"(v.w) : "l"(p));
    return v;
}
// Table gather: 32B load with L2 evict_last (sticky). Legal form on sm_103.
struct F8 { float f[8]; };
__device__ __forceinline__ F8 ld_table_f8(const float* p) {
    unsigned long long a, b, c, d;
    asm volatile("ld.global.nc.L2::evict_last.v4.b64 {%0,%1,%2,%3}, [%4];"
                 : "=l"(a), "=l"(b), "=l"(c), "=l"(d) : "l"(p));
    F8 r;
    r.f[0] = __uint_as_float((unsigned)a); r.f[1] = __uint_as_float((unsigned)(a >> 32));
    r.f[2] = __uint_as_float((unsigned)b); r.f[3] = __uint_as_float((unsigned)(b >> 32));
    r.f[4] = __uint_as_float((unsigned)c); r.f[5] = __uint_as_float((unsigned)(c >> 32));
    r.f[6] = __uint_as_float((unsigned)d); r.f[7] = __uint_as_float((unsigned)(d >> 32));
    return r;
}

// ---------------------------------------------------------------------------
// Kernel 1: transpose ft_w [256, 40960] -> g_ftw_t [40960, 256] (vectorized)
// ---------------------------------------------------------------------------
__global__ void __launch_bounds__(256) transpose_kernel(const float* __restrict__ ft_w) {
    __shared__ float tile[32][33];
    int j0 = blockIdx.x * 32;
    int h0 = blockIdx.y * 32;
    int tx = threadIdx.x;       // 0..7
    int ty = threadIdx.y;       // 0..31

    float4 v = *(const float4*)&ft_w[(size_t)(h0 + ty) * FEAT + j0 + 4 * tx];
    tile[4 * tx + 0][ty] = v.x;
    tile[4 * tx + 1][ty] = v.y;
    tile[4 * tx + 2][ty] = v.z;
    tile[4 * tx + 3][ty] = v.w;
    __syncthreads();

    float4 o;
    o.x = tile[ty][4 * tx + 0];
    o.y = tile[ty][4 * tx + 1];
    o.z = tile[ty][4 * tx + 2];
    o.w = tile[ty][4 * tx + 3];
    *(float4*)&g_ftw_t[(size_t)(j0 + ty) * H1 + h0 + 4 * tx] = o;
}

// ---------------------------------------------------------------------------
// Kernel 2 (persistent): loop over 8192 (row,side) tasks. Per task: float4
// streaming scan -> nonzero extraction -> warp-parallel gather (32B/lane,
// evict_last) -> cross-warp reduce -> bias + crelu -> g_x.
// ---------------------------------------------------------------------------
__global__ void __launch_bounds__(256) ft_kernel(
    const float* __restrict__ wf, const float* __restrict__ bf,
    const float* __restrict__ ft_b)
{
    __shared__ int   s_idx[CAP];
    __shared__ float s_val[CAP];
    __shared__ int   s_count;
    __shared__ float s_red[8][256];

    int tid  = threadIdx.x;
    int warp = tid >> 5, lane = tid & 31;
    float bias = ft_b[tid];

    for (int task = blockIdx.x; task < 2 * BATCH; task += FT_BLOCKS) {
        int row  = task >> 1;
        int side = task & 1;
        const float* feats = side ? bf : wf;
        const float4* frow = (const float4*)(feats + (size_t)row * FEAT);

        if (tid == 0) s_count = 0;
        __syncthreads();

        // Coalesced streaming scan: 10240 float4 / 256 threads = 40 iters
#pragma unroll 8
        for (int i = tid; i < FEAT / 4; i += 256) {
            float4 v = ld_stream_f4(&frow[i]);
            if (v.x != 0.f) { int p = atomicAdd(&s_count, 1); if (p < CAP) { s_idx[p] = 4 * i;     s_val[p] = v.x; } }
            if (v.y != 0.f) { int p = atomicAdd(&s_count, 1); if (p < CAP) { s_idx[p] = 4 * i + 1; s_val[p] = v.y; } }
            if (v.z != 0.f) { int p = atomicAdd(&s_count, 1); if (p < CAP) { s_idx[p] = 4 * i + 2; s_val[p] = v.z; } }
            if (v.w != 0.f) { int p = atomicAdd(&s_count, 1); if (p < CAP) { s_idx[p] = 4 * i + 3; s_val[p] = v.w; } }
        }
        __syncthreads();

        int n = min(s_count, CAP);

        // Warp w handles nonzeros k = w, w+8, ... Lane owns h = lane*8..+7.
        float acc[8];
#pragma unroll
        for (int j = 0; j < 8; j++) acc[j] = 0.f;

        for (int k = warp; k < n; k += 8) {
            float v = s_val[k];
            F8 t = ld_table_f8(&g_ftw_t[(size_t)s_idx[k] * H1 + lane * 8]);
#pragma unroll
            for (int j = 0; j < 8; j++) acc[j] = fmaf(v, t.f[j], acc[j]);
        }

#pragma unroll
        for (int j = 0; j < 8; j++) s_red[warp][lane * 8 + j] = acc[j];
        __syncthreads();

        float r = bias;
#pragma unroll
        for (int w = 0; w < 8; w++) r += s_red[w][tid];
        r = fminf(fmaxf(r, 0.f), 1.f);
        g_x[(size_t)row * 512 + side * 256 + tid] = r;
        __syncthreads();   // protect s_idx/s_val/s_count before next task
    }
}

// ---------------------------------------------------------------------------
// Kernel 3: tail MLP. fc1_w staged in 64KB smem, 16 rows per 256-thread block
// (2 rows per warp). 256 blocks total -> fc1_w L2 traffic 256MB -> 16MB.
// ---------------------------------------------------------------------------
#define MLP_ROWS 16
__global__ void __launch_bounds__(256) mlp_kernel(
    const float* __restrict__ fc1_w, const float* __restrict__ fc1_b,
    const float* __restrict__ fc2_w, const float* __restrict__ fc2_b,
    const float* __restrict__ fc3_w, const float* __restrict__ fc3_b,
    float* __restrict__ out)
{
    __shared__ float s_fc1[32 * 512];  // 64 KB
    __shared__ float fc2t[32 * 32];    // transposed: [j][h]
    __shared__ float s_fc3[32];
    __shared__ float s_b1[32];
    int tid = threadIdx.x;

    // Stage weights
    for (int i = tid; i < 32 * 512 / 4; i += 256)
        *(float4*)&s_fc1[4 * i] = *(const float4*)&fc1_w[4 * i];
    for (int i = tid; i < 1024; i += 256) {
        int h = i >> 5, j = i & 31;
        fc2t[j * 32 + h] = fc2_w[i];
    }
    if (tid < 32) { s_fc3[tid] = fc3_w[tid]; s_b1[tid] = fc1_b[tid]; }
    __syncthreads();

    int warp = tid >> 5, lane = tid & 31;

#pragma unroll
    for (int rr = 0; rr < 2; rr++) {
        int row = blockIdx.x * MLP_ROWS + warp * 2 + rr;

        const float* xr = g_x + (size_t)row * 512;
        float xv[16];
#pragma unroll
        for (int k = 0; k < 16; k++) xv[k] = xr[lane + 32 * k];

        float y1 = 0.f;
#pragma unroll
        for (int h = 0; h < 32; h++) {
            const float* w = &s_fc1[h * 512];
            float p = 0.f;
#pragma unroll
            for (int k = 0; k < 16; k++) p = fmaf(w[lane + 32 * k], xv[k], p);
#pragma unroll
            for (int o = 16; o; o >>= 1) p += __shfl_xor_sync(0xffffffffu, p, o);
            p += s_b1[h];
            p = fminf(fmaxf(p, 0.f), 1.f);
            if (lane == h) y1 = p;
        }

        float y2 = fc2_b[lane];
#pragma unroll
        for (int j = 0; j < 32; j++) {
            float xj = __shfl_sync(0xffffffffu, y1, j);
            y2 = fmaf(fc2t[j * 32 + lane], xj, y2);
        }
        y2 = fminf(fmaxf(y2, 0.f), 1.f);

        float p3 = s_fc3[lane] * y2;
#pragma unroll
        for (int o = 16; o; o >>= 1) p3 += __shfl_xor_sync(0xffffffffu, p3, o);
        if (lane == 0) out[row] = p3 + fc3_b[0];
    }
}

// ---------------------------------------------------------------------------
extern "C" void kernel_launch(void* const* d_in, const int* in_sizes, int n_in,
                              void* d_out, int out_size) {
    const float* wf    = (const float*)d_in[0];
    const float* bf    = (const float*)d_in[1];
    const float* ft_w  = (const float*)d_in[2];
    const float* ft_b  = (const float*)d_in[3];
    const float* fc1_w = (const float*)d_in[4];
    const float* fc1_b = (const float*)d_in[5];
    const float* fc2_w = (const float*)d_in[6];
    const float* fc2_b = (const float*)d_in[7];
    const float* fc3_w = (const float*)d_in[8];
    const float* fc3_b = (const float*)d_in[9];
    float* out = (float*)d_out;

    dim3 tb(8, 32);
    dim3 tg(FEAT / 32, H1 / 32);
    transpose_kernel<<<tg, tb>>>(ft_w);

    ft_kernel<<<FT_BLOCKS, 256>>>(wf, bf, ft_b);

    mlp_kernel<<<BATCH / MLP_ROWS, 256>>>(fc1_w, fc1_b, fc2_w, fc2_b, fc3_w, fc3_b, out);
}

// round 6
// speedup vs baseline: 1.0841x; 1.0662x over previous
#include <cuda_runtime.h>

#define BATCH 4096
#define FEAT 40960
#define H1 256
#define CAP 256        // max nonzeros buffered per row (actual data has <=30)
#define NTILES (FEAT / 32 * H1 / 32)   // 10240 transpose tiles (32x32)
#define JTILES (FEAT / 32)             // 1280
#define TCHUNK 16
#define GATE 2048      // only bids < GATE participate in transpose stealing

// Scratch (no allocation allowed)
__device__ __align__(128) float g_ftw_t[(size_t)FEAT * H1];  // 42 MB, [feature][h]
__device__ __align__(128) float g_x[(size_t)BATCH * 2 * H1]; // 8 MB,  [row][512]

// Work-stealing / completion counters (reset by last-finishing block each run)
__device__ int g_claim = 0;   // next tile chunk to claim
__device__ int g_done  = 0;   // tiles completed
__device__ int g_fin   = 0;   // ft blocks finished

// Streaming float4 load: evict-first (don't displace the table in L2)
__device__ __forceinline__ float4 ld_stream_f4(const float4* p) {
    float4 v;
    asm volatile("ld.global.cs.v4.f32 {%0,%1,%2,%3}, [%4];"
                 : "=f"(v.x), "=f"(v.y), "=f"(v.z), "=f"(v.w) : "l"(p));
    return v;
}
// Table gather: 32B load with L2 evict_last (sticky)
struct F8 { float f[8]; };
__device__ __forceinline__ F8 ld_table_f8(const float* p) {
    unsigned long long a, b, c, d;
    asm volatile("ld.global.nc.L2::evict_last.v4.b64 {%0,%1,%2,%3}, [%4];"
                 : "=l"(a), "=l"(b), "=l"(c), "=l"(d) : "l"(p));
    F8 r;
    r.f[0] = __uint_as_float((unsigned)a); r.f[1] = __uint_as_float((unsigned)(a >> 32));
    r.f[2] = __uint_as_float((unsigned)b); r.f[3] = __uint_as_float((unsigned)(b >> 32));
    r.f[4] = __uint_as_float((unsigned)c); r.f[5] = __uint_as_float((unsigned)(c >> 32));
    r.f[6] = __uint_as_float((unsigned)d); r.f[7] = __uint_as_float((unsigned)(d >> 32));
    return r;
}

// ---------------------------------------------------------------------------
// Fused kernel: [optional transpose work-stealing] -> streaming scan ->
// wait table ready -> warp-parallel gather -> reduce -> bias+crelu -> g_x.
// One block (256 threads = 8 warps) per (row, side) task; grid = 8192.
// ---------------------------------------------------------------------------
__global__ void __launch_bounds__(256) ft_kernel(
    const float* __restrict__ wf, const float* __restrict__ bf,
    const float* __restrict__ ft_w, const float* __restrict__ ft_b)
{
    __shared__ union {
        float tile[32][33];   // transpose staging (4.2 KB)
        float red[8][256];    // cross-warp reduction (8 KB)
    } u;
    __shared__ int   s_idx[CAP];
    __shared__ float s_val[CAP];
    __shared__ int   s_count;
    __shared__ int   s_t0;

    int bid  = blockIdx.x;
    int tid  = threadIdx.x;
    int warp = tid >> 5, lane = tid & 31;

    // ---- Phase 0: transpose work-stealing (progress needs only RUNNING blocks)
    if (bid < GATE) {
        for (;;) {
            if (tid == 0) s_t0 = atomicAdd(&g_claim, TCHUNK);
            __syncthreads();
            int t0 = s_t0;
            if (t0 >= NTILES) break;
            int tend = min(t0 + TCHUNK, NTILES);
            int tx = tid & 7, ty = tid >> 3;      // (8,32) tile layout
            for (int t = t0; t < tend; t++) {
                int j0 = (t % JTILES) * 32;
                int h0 = (t / JTILES) * 32;
                float4 v = *(const float4*)&ft_w[(size_t)(h0 + ty) * FEAT + j0 + 4 * tx];
                u.tile[4 * tx + 0][ty] = v.x;
                u.tile[4 * tx + 1][ty] = v.y;
                u.tile[4 * tx + 2][ty] = v.z;
                u.tile[4 * tx + 3][ty] = v.w;
                __syncthreads();
                float4 o;
                o.x = u.tile[ty][4 * tx + 0];
                o.y = u.tile[ty][4 * tx + 1];
                o.z = u.tile[ty][4 * tx + 2];
                o.w = u.tile[ty][4 * tx + 3];
                *(float4*)&g_ftw_t[(size_t)(j0 + ty) * H1 + h0 + 4 * tx] = o;
                __syncthreads();
            }
            __threadfence();                       // release table writes
            if (tid == 0) atomicAdd(&g_done, tend - t0);
        }
    }

    // ---- Phase 1: streaming scan (does not need the table)
    int row  = bid >> 1;
    int side = bid & 1;
    const float* feats = side ? bf : wf;
    const float4* frow = (const float4*)(feats + (size_t)row * FEAT);

    if (tid == 0) s_count = 0;
    __syncthreads();

#pragma unroll 8
    for (int i = tid; i < FEAT / 4; i += 256) {
        float4 v = ld_stream_f4(&frow[i]);
        if (v.x != 0.f) { int p = atomicAdd(&s_count, 1); if (p < CAP) { s_idx[p] = 4 * i;     s_val[p] = v.x; } }
        if (v.y != 0.f) { int p = atomicAdd(&s_count, 1); if (p < CAP) { s_idx[p] = 4 * i + 1; s_val[p] = v.y; } }
        if (v.z != 0.f) { int p = atomicAdd(&s_count, 1); if (p < CAP) { s_idx[p] = 4 * i + 2; s_val[p] = v.z; } }
        if (v.w != 0.f) { int p = atomicAdd(&s_count, 1); if (p < CAP) { s_idx[p] = 4 * i + 3; s_val[p] = v.w; } }
    }

    // ---- Barrier: table must be complete before gathering
    if (tid == 0) {
        while (atomicAdd(&g_done, 0) < NTILES) { }
    }
    __syncthreads();

    int n = min(s_count, CAP);

    // ---- Phase 2: gather. Warp w takes nonzeros k = w, w+8, ...; lane owns h = lane*8..+7.
    float acc[8];
#pragma unroll
    for (int j = 0; j < 8; j++) acc[j] = 0.f;

    for (int k = warp; k < n; k += 8) {
        float v = s_val[k];
        F8 t = ld_table_f8(&g_ftw_t[(size_t)s_idx[k] * H1 + lane * 8]);
#pragma unroll
        for (int j = 0; j < 8; j++) acc[j] = fmaf(v, t.f[j], acc[j]);
    }

#pragma unroll
    for (int j = 0; j < 8; j++) u.red[warp][lane * 8 + j] = acc[j];
    __syncthreads();

    float r = ft_b[tid];
#pragma unroll
    for (int w = 0; w < 8; w++) r += u.red[w][tid];
    r = fminf(fmaxf(r, 0.f), 1.f);
    g_x[(size_t)row * 512 + side * 256 + tid] = r;

    // ---- Reset counters for next graph replay (last block only)
    __syncthreads();
    if (tid == 0) {
        int f = atomicAdd(&g_fin, 1);
        if (f == 2 * BATCH - 1) {
            g_claim = 0; g_done = 0; g_fin = 0;
            __threadfence();
        }
    }
}

// ---------------------------------------------------------------------------
// Tail MLP (R3 form): one warp per batch row, 8 rows per 256-thread block.
// fc1_w is L1-resident per block (64KB <= 228KB L1).
// ---------------------------------------------------------------------------
__global__ void __launch_bounds__(256) mlp_kernel(
    const float* __restrict__ fc1_w, const float* __restrict__ fc1_b,
    const float* __restrict__ fc2_w, const float* __restrict__ fc2_b,
    const float* __restrict__ fc3_w, const float* __restrict__ fc3_b,
    float* __restrict__ out)
{
    __shared__ float fc2t[32 * 32];   // transposed: [j][h]
    __shared__ float s_fc3[32];
    int tid = threadIdx.x;

    for (int i = tid; i < 1024; i += 256) {
        int h = i >> 5, j = i & 31;
        fc2t[j * 32 + h] = fc2_w[i];
    }
    if (tid < 32) s_fc3[tid] = fc3_w[tid];
    __syncthreads();

    int warp = tid >> 5, lane = tid & 31;
    int row = blockIdx.x * 8 + warp;

    const float* xr = g_x + (size_t)row * 512;
    float xv[16];
#pragma unroll
    for (int k = 0; k < 16; k++) xv[k] = xr[lane + 32 * k];

    float y1 = 0.f;
#pragma unroll
    for (int h = 0; h < 32; h++) {
        const float* w = fc1_w + h * 512;
        float p = 0.f;
#pragma unroll
        for (int k = 0; k < 16; k++) p = fmaf(__ldg(&w[lane + 32 * k]), xv[k], p);
#pragma unroll
        for (int o = 16; o; o >>= 1) p += __shfl_xor_sync(0xffffffffu, p, o);
        p += fc1_b[h];
        p = fminf(fmaxf(p, 0.f), 1.f);
        if (lane == h) y1 = p;
    }

    float y2 = fc2_b[lane];
#pragma unroll
    for (int j = 0; j < 32; j++) {
        float xj = __shfl_sync(0xffffffffu, y1, j);
        y2 = fmaf(fc2t[j * 32 + lane], xj, y2);
    }
    y2 = fminf(fmaxf(y2, 0.f), 1.f);

    float p3 = s_fc3[lane] * y2;
#pragma unroll
    for (int o = 16; o; o >>= 1) p3 += __shfl_xor_sync(0xffffffffu, p3, o);
    if (lane == 0) out[row] = p3 + fc3_b[0];
}

// ---------------------------------------------------------------------------
extern "C" void kernel_launch(void* const* d_in, const int* in_sizes, int n_in,
                              void* d_out, int out_size) {
    const float* wf    = (const float*)d_in[0];
    const float* bf    = (const float*)d_in[1];
    const float* ft_w  = (const float*)d_in[2];
    const float* ft_b  = (const float*)d_in[3];
    const float* fc1_w = (const float*)d_in[4];
    const float* fc1_b = (const float*)d_in[5];
    const float* fc2_w = (const float*)d_in[6];
    const float* fc2_b = (const float*)d_in[7];
    const float* fc3_w = (const float*)d_in[8];
    const float* fc3_b = (const float*)d_in[9];
    float* out = (float*)d_out;

    ft_kernel<<<2 * BATCH, 256>>>(wf, bf, ft_w, ft_b);
    mlp_kernel<<<BATCH / 8, 256>>>(fc1_w, fc1_b, fc2_w, fc2_b, fc3_w, fc3_b, out);
}

// round 7
// speedup vs baseline: 1.1688x; 1.0781x over previous
#include <cuda_runtime.h>

#define BATCH 4096
#define FEAT 40960
#define H1 256
#define CAP 256        // max nonzeros buffered per row (actual data has <=30)
#define NTILES (FEAT / 32 * H1 / 32)   // 10240 transpose tiles (32x32)
#define JTILES (FEAT / 32)             // 1280
#define TCHUNK 16
#define GATE 2048      // only bids < GATE participate in transpose stealing

// Scratch (no allocation allowed)
__device__ __align__(128) float g_ftw_t[(size_t)FEAT * H1];  // 42 MB, [feature][h]
__device__ __align__(128) float g_x[(size_t)BATCH * 2 * H1]; // 8 MB,  [row][512]

// Work-stealing / completion counters (reset by last-finishing block each run)
__device__ int g_claim = 0;
__device__ int g_done  = 0;
__device__ int g_fin   = 0;

// Streaming float4 load: evict-first (don't displace the table in L2)
__device__ __forceinline__ float4 ld_stream_f4(const float4* p) {
    float4 v;
    asm volatile("ld.global.cs.v4.f32 {%0,%1,%2,%3}, [%4];"
                 : "=f"(v.x), "=f"(v.y), "=f"(v.z), "=f"(v.w) : "l"(p));
    return v;
}
// Table gather: 32B load with L2 evict_last (sticky)
struct F8 { float f[8]; };
__device__ __forceinline__ F8 ld_table_f8(const float* p) {
    unsigned long long a, b, c, d;
    asm volatile("ld.global.nc.L2::evict_last.v4.b64 {%0,%1,%2,%3}, [%4];"
                 : "=l"(a), "=l"(b), "=l"(c), "=l"(d) : "l"(p));
    F8 r;
    r.f[0] = __uint_as_float((unsigned)a); r.f[1] = __uint_as_float((unsigned)(a >> 32));
    r.f[2] = __uint_as_float((unsigned)b); r.f[3] = __uint_as_float((unsigned)(b >> 32));
    r.f[4] = __uint_as_float((unsigned)c); r.f[5] = __uint_as_float((unsigned)(c >> 32));
    r.f[6] = __uint_as_float((unsigned)d); r.f[7] = __uint_as_float((unsigned)(d >> 32));
    return r;
}

// ---------------------------------------------------------------------------
// Fused FT kernel (R6 winner, unchanged): [transpose work-stealing] -> scan
// -> wait table -> gather -> reduce -> bias+crelu -> g_x.
// ---------------------------------------------------------------------------
__global__ void __launch_bounds__(256) ft_kernel(
    const float* __restrict__ wf, const float* __restrict__ bf,
    const float* __restrict__ ft_w, const float* __restrict__ ft_b)
{
    __shared__ union {
        float tile[32][33];
        float red[8][256];
    } u;
    __shared__ int   s_idx[CAP];
    __shared__ float s_val[CAP];
    __shared__ int   s_count;
    __shared__ int   s_t0;

    int bid  = blockIdx.x;
    int tid  = threadIdx.x;
    int warp = tid >> 5, lane = tid & 31;

    if (bid < GATE) {
        for (;;) {
            if (tid == 0) s_t0 = atomicAdd(&g_claim, TCHUNK);
            __syncthreads();
            int t0 = s_t0;
            if (t0 >= NTILES) break;
            int tend = min(t0 + TCHUNK, NTILES);
            int tx = tid & 7, ty = tid >> 3;
            for (int t = t0; t < tend; t++) {
                int j0 = (t % JTILES) * 32;
                int h0 = (t / JTILES) * 32;
                float4 v = *(const float4*)&ft_w[(size_t)(h0 + ty) * FEAT + j0 + 4 * tx];
                u.tile[4 * tx + 0][ty] = v.x;
                u.tile[4 * tx + 1][ty] = v.y;
                u.tile[4 * tx + 2][ty] = v.z;
                u.tile[4 * tx + 3][ty] = v.w;
                __syncthreads();
                float4 o;
                o.x = u.tile[ty][4 * tx + 0];
                o.y = u.tile[ty][4 * tx + 1];
                o.z = u.tile[ty][4 * tx + 2];
                o.w = u.tile[ty][4 * tx + 3];
                *(float4*)&g_ftw_t[(size_t)(j0 + ty) * H1 + h0 + 4 * tx] = o;
                __syncthreads();
            }
            __threadfence();
            if (tid == 0) atomicAdd(&g_done, tend - t0);
        }
    }

    int row  = bid >> 1;
    int side = bid & 1;
    const float* feats = side ? bf : wf;
    const float4* frow = (const float4*)(feats + (size_t)row * FEAT);

    if (tid == 0) s_count = 0;
    __syncthreads();

#pragma unroll 8
    for (int i = tid; i < FEAT / 4; i += 256) {
        float4 v = ld_stream_f4(&frow[i]);
        if (v.x != 0.f) { int p = atomicAdd(&s_count, 1); if (p < CAP) { s_idx[p] = 4 * i;     s_val[p] = v.x; } }
        if (v.y != 0.f) { int p = atomicAdd(&s_count, 1); if (p < CAP) { s_idx[p] = 4 * i + 1; s_val[p] = v.y; } }
        if (v.z != 0.f) { int p = atomicAdd(&s_count, 1); if (p < CAP) { s_idx[p] = 4 * i + 2; s_val[p] = v.z; } }
        if (v.w != 0.f) { int p = atomicAdd(&s_count, 1); if (p < CAP) { s_idx[p] = 4 * i + 3; s_val[p] = v.w; } }
    }

    if (tid == 0) {
        while (atomicAdd(&g_done, 0) < NTILES) { }
    }
    __syncthreads();

    int n = min(s_count, CAP);

    float acc[8];
#pragma unroll
    for (int j = 0; j < 8; j++) acc[j] = 0.f;

    for (int k = warp; k < n; k += 8) {
        float v = s_val[k];
        F8 t = ld_table_f8(&g_ftw_t[(size_t)s_idx[k] * H1 + lane * 8]);
#pragma unroll
        for (int j = 0; j < 8; j++) acc[j] = fmaf(v, t.f[j], acc[j]);
    }

#pragma unroll
    for (int j = 0; j < 8; j++) u.red[warp][lane * 8 + j] = acc[j];
    __syncthreads();

    float r = ft_b[tid];
#pragma unroll
    for (int w = 0; w < 8; w++) r += u.red[w][tid];
    r = fminf(fmaxf(r, 0.f), 1.f);
    g_x[(size_t)row * 512 + side * 256 + tid] = r;

    __syncthreads();
    if (tid == 0) {
        int f = atomicAdd(&g_fin, 1);
        if (f == 2 * BATCH - 1) {
            g_claim = 0; g_done = 0; g_fin = 0;
            __threadfence();
        }
    }
}

// ---------------------------------------------------------------------------
// Tail MLP, restructured: thread = (row, h) pair, NO shuffles in fc1.
// 256 blocks x 16 rows. lane = h; warp w owns local rows {w, w+8}.
// fc1_w staged in dynamic smem [32][516] (pad 4 -> conflict-free LDS.128).
// x read as same-address float4 LDG broadcast (L1-resident, 2KB/row).
// ---------------------------------------------------------------------------
#define MLP_ROWS 16
#define W1_PITCH 516                    // floats per h row (512 + 4 pad)
#define MLP_SMEM (32 * W1_PITCH * 4)    // 66048 bytes

__global__ void __launch_bounds__(256) mlp_kernel(
    const float* __restrict__ fc1_w, const float* __restrict__ fc1_b,
    const float* __restrict__ fc2_w, const float* __restrict__ fc2_b,
    const float* __restrict__ fc3_w, const float* __restrict__ fc3_b,
    float* __restrict__ out)
{
    extern __shared__ float s_w1[];       // [32][W1_PITCH]
    __shared__ float fc2t[32 * 32];       // [j][h2]
    __shared__ float s_y1[MLP_ROWS][32];
    __shared__ float s_b1[32], s_b2[32], s_fc3[32];

    int tid = threadIdx.x;

    // Stage fc1_w [32][512] row h -> s_w1[h*W1_PITCH + ...], coalesced float4.
    for (int i = tid; i < 32 * 128; i += 256) {
        int h = i >> 7, j4 = i & 127;
        *(float4*)&s_w1[h * W1_PITCH + 4 * j4] = ((const float4*)fc1_w)[i];
    }
    for (int i = tid; i < 1024; i += 256) {
        int h2 = i >> 5, j = i & 31;
        fc2t[j * 32 + h2] = fc2_w[i];
    }
    if (tid < 32) { s_b1[tid] = fc1_b[tid]; s_b2[tid] = fc2_b[tid]; s_fc3[tid] = fc3_w[tid]; }
    __syncthreads();

    int warp = tid >> 5, lane = tid & 31;

    // fc1: each thread computes y1[row][lane] via straight 512-FMA dot.
#pragma unroll
    for (int rr = 0; rr < 2; rr++) {
        int r = warp + 8 * rr;
        int row = blockIdx.x * MLP_ROWS + r;
        const float4* xr = (const float4*)(g_x + (size_t)row * 512);
        const float4* wr = (const float4*)&s_w1[lane * W1_PITCH];
        float4 a0 = make_float4(0.f, 0.f, 0.f, 0.f);
        float4 a1 = make_float4(0.f, 0.f, 0.f, 0.f);
#pragma unroll 8
        for (int j4 = 0; j4 < 128; j4 += 2) {
            float4 w0 = wr[j4],     x0 = xr[j4];
            float4 w1 = wr[j4 + 1], x1 = xr[j4 + 1];
            a0.x = fmaf(w0.x, x0.x, a0.x); a0.y = fmaf(w0.y, x0.y, a0.y);
            a0.z = fmaf(w0.z, x0.z, a0.z); a0.w = fmaf(w0.w, x0.w, a0.w);
            a1.x = fmaf(w1.x, x1.x, a1.x); a1.y = fmaf(w1.y, x1.y, a1.y);
            a1.z = fmaf(w1.z, x1.z, a1.z); a1.w = fmaf(w1.w, x1.w, a1.w);
        }
        float p = (a0.x + a0.y) + (a0.z + a0.w) + (a1.x + a1.y) + (a1.z + a1.w);
        p += s_b1[lane];
        s_y1[r][lane] = fminf(fmaxf(p, 0.f), 1.f);
    }
    __syncthreads();

    // fc2 + fc3: lane = h2 owns output; smem broadcast of y1; one shuffle reduce.
#pragma unroll
    for (int rr = 0; rr < 2; rr++) {
        int r = warp + 8 * rr;
        int row = blockIdx.x * MLP_ROWS + r;
        float y2 = s_b2[lane];
#pragma unroll
        for (int j = 0; j < 32; j++)
            y2 = fmaf(fc2t[j * 32 + lane], s_y1[r][j], y2);
        y2 = fminf(fmaxf(y2, 0.f), 1.f);

        float p3 = s_fc3[lane] * y2;
#pragma unroll
        for (int o = 16; o; o >>= 1) p3 += __shfl_xor_sync(0xffffffffu, p3, o);
        if (lane == 0) out[row] = p3 + fc3_b[0];
    }
}

// ---------------------------------------------------------------------------
extern "C" void kernel_launch(void* const* d_in, const int* in_sizes, int n_in,
                              void* d_out, int out_size) {
    const float* wf    = (const float*)d_in[0];
    const float* bf    = (const float*)d_in[1];
    const float* ft_w  = (const float*)d_in[2];
    const float* ft_b  = (const float*)d_in[3];
    const float* fc1_w = (const float*)d_in[4];
    const float* fc1_b = (const float*)d_in[5];
    const float* fc2_w = (const float*)d_in[6];
    const float* fc2_b = (const float*)d_in[7];
    const float* fc3_w = (const float*)d_in[8];
    const float* fc3_b = (const float*)d_in[9];
    float* out = (float*)d_out;

    static int smem_set = 0;
    if (!smem_set) {
        cudaFuncSetAttribute(mlp_kernel,
                             cudaFuncAttributeMaxDynamicSharedMemorySize, MLP_SMEM);
        smem_set = 1;
    }

    ft_kernel<<<2 * BATCH, 256>>>(wf, bf, ft_w, ft_b);
    mlp_kernel<<<BATCH / MLP_ROWS, 256, MLP_SMEM>>>(
        fc1_w, fc1_b, fc2_w, fc2_b, fc3_w, fc3_b, out);
}

// round 8
// speedup vs baseline: 1.2808x; 1.0958x over previous
#include <cuda_runtime.h>

#define BATCH 4096
#define FEAT 40960
#define H1 256
#define CAP 256        // max nonzeros buffered per row (actual data has <=30)
#define NTILES (FEAT / 32 * H1 / 32)   // 10240 transpose tiles (32x32)
#define JTILES (FEAT / 32)             // 1280
#define TCHUNK 16
#define GATE 2048      // only bids < GATE participate in transpose stealing

// Scratch (no allocation allowed)
__device__ __align__(128) float g_ftw_t[(size_t)FEAT * H1];  // 42 MB, [feature][h]
__device__ __align__(128) float g_x[(size_t)BATCH * 2 * H1]; // 8 MB,  [row][512]

// Work-stealing / completion counters (self-resetting each run)
__device__ int g_claim = 0;
__device__ int g_done  = 0;
__device__ int g_fin   = 0;
__device__ int g_row_done[BATCH];   // zero-init; reset by the consumer block

// Streaming float4 load: evict-first (don't displace the table in L2)
__device__ __forceinline__ float4 ld_stream_f4(const float4* p) {
    float4 v;
    asm volatile("ld.global.cs.v4.f32 {%0,%1,%2,%3}, [%4];"
                 : "=f"(v.x), "=f"(v.y), "=f"(v.z), "=f"(v.w) : "l"(p));
    return v;
}
// L2-coherent float4 load (bypass L1) for cross-block g_x reads
__device__ __forceinline__ float4 ld_cg_f4(const float4* p) {
    float4 v;
    asm volatile("ld.global.cg.v4.f32 {%0,%1,%2,%3}, [%4];"
                 : "=f"(v.x), "=f"(v.y), "=f"(v.z), "=f"(v.w) : "l"(p));
    return v;
}
// Table gather: 32B load with L2 evict_last (sticky)
struct F8 { float f[8]; };
__device__ __forceinline__ F8 ld_table_f8(const float* p) {
    unsigned long long a, b, c, d;
    asm volatile("ld.global.nc.L2::evict_last.v4.b64 {%0,%1,%2,%3}, [%4];"
                 : "=l"(a), "=l"(b), "=l"(c), "=l"(d) : "l"(p));
    F8 r;
    r.f[0] = __uint_as_float((unsigned)a); r.f[1] = __uint_as_float((unsigned)(a >> 32));
    r.f[2] = __uint_as_float((unsigned)b); r.f[3] = __uint_as_float((unsigned)(b >> 32));
    r.f[4] = __uint_as_float((unsigned)c); r.f[5] = __uint_as_float((unsigned)(c >> 32));
    r.f[6] = __uint_as_float((unsigned)d); r.f[7] = __uint_as_float((unsigned)(d >> 32));
    return r;
}

// ---------------------------------------------------------------------------
// Single fused kernel: [transpose work-stealing] -> scan -> wait table ->
// gather -> reduce -> bias+crelu -> g_x -> [second finisher per row: full MLP]
// One block (256 threads = 8 warps) per (row, side) task; grid = 8192.
// ---------------------------------------------------------------------------
__global__ void __launch_bounds__(256) ft_kernel(
    const float* __restrict__ wf, const float* __restrict__ bf,
    const float* __restrict__ ft_w, const float* __restrict__ ft_b,
    const float* __restrict__ fc1_w, const float* __restrict__ fc1_b,
    const float* __restrict__ fc2_w, const float* __restrict__ fc2_b,
    const float* __restrict__ fc3_w, const float* __restrict__ fc3_b,
    float* __restrict__ out)
{
    __shared__ union {
        float tile[32][33];
        float red[8][256];
    } u;
    __shared__ int   s_idx[CAP];
    __shared__ float s_val[CAP];
    __shared__ int   s_count;
    __shared__ int   s_t0;
    __shared__ int   s_do_mlp;
    __shared__ float s_y1[32];

    int bid  = blockIdx.x;
    int tid  = threadIdx.x;
    int warp = tid >> 5, lane = tid & 31;

    // ---- Phase 0: transpose work-stealing
    if (bid < GATE) {
        for (;;) {
            if (tid == 0) s_t0 = atomicAdd(&g_claim, TCHUNK);
            __syncthreads();
            int t0 = s_t0;
            if (t0 >= NTILES) break;
            int tend = min(t0 + TCHUNK, NTILES);
            int tx = tid & 7, ty = tid >> 3;
            for (int t = t0; t < tend; t++) {
                int j0 = (t % JTILES) * 32;
                int h0 = (t / JTILES) * 32;
                float4 v = *(const float4*)&ft_w[(size_t)(h0 + ty) * FEAT + j0 + 4 * tx];
                u.tile[4 * tx + 0][ty] = v.x;
                u.tile[4 * tx + 1][ty] = v.y;
                u.tile[4 * tx + 2][ty] = v.z;
                u.tile[4 * tx + 3][ty] = v.w;
                __syncthreads();
                float4 o;
                o.x = u.tile[ty][4 * tx + 0];
                o.y = u.tile[ty][4 * tx + 1];
                o.z = u.tile[ty][4 * tx + 2];
                o.w = u.tile[ty][4 * tx + 3];
                *(float4*)&g_ftw_t[(size_t)(j0 + ty) * H1 + h0 + 4 * tx] = o;
                __syncthreads();
            }
            __threadfence();
            if (tid == 0) atomicAdd(&g_done, tend - t0);
        }
    }

    // ---- Phase 1: streaming scan
    int row  = bid >> 1;
    int side = bid & 1;
    const float* feats = side ? bf : wf;
    const float4* frow = (const float4*)(feats + (size_t)row * FEAT);

    if (tid == 0) s_count = 0;
    __syncthreads();

#pragma unroll 8
    for (int i = tid; i < FEAT / 4; i += 256) {
        float4 v = ld_stream_f4(&frow[i]);
        if (v.x != 0.f) { int p = atomicAdd(&s_count, 1); if (p < CAP) { s_idx[p] = 4 * i;     s_val[p] = v.x; } }
        if (v.y != 0.f) { int p = atomicAdd(&s_count, 1); if (p < CAP) { s_idx[p] = 4 * i + 1; s_val[p] = v.y; } }
        if (v.z != 0.f) { int p = atomicAdd(&s_count, 1); if (p < CAP) { s_idx[p] = 4 * i + 2; s_val[p] = v.z; } }
        if (v.w != 0.f) { int p = atomicAdd(&s_count, 1); if (p < CAP) { s_idx[p] = 4 * i + 3; s_val[p] = v.w; } }
    }

    // ---- Barrier: table complete before gathering
    if (tid == 0) {
        while (atomicAdd(&g_done, 0) < NTILES) { }
    }
    __syncthreads();

    int n = min(s_count, CAP);

    // ---- Phase 2: gather
    float acc[8];
#pragma unroll
    for (int j = 0; j < 8; j++) acc[j] = 0.f;

    for (int k = warp; k < n; k += 8) {
        float v = s_val[k];
        F8 t = ld_table_f8(&g_ftw_t[(size_t)s_idx[k] * H1 + lane * 8]);
#pragma unroll
        for (int j = 0; j < 8; j++) acc[j] = fmaf(v, t.f[j], acc[j]);
    }

#pragma unroll
    for (int j = 0; j < 8; j++) u.red[warp][lane * 8 + j] = acc[j];
    __syncthreads();

    float r = ft_b[tid];
#pragma unroll
    for (int w = 0; w < 8; w++) r += u.red[w][tid];
    r = fminf(fmaxf(r, 0.f), 1.f);
    g_x[(size_t)row * 512 + side * 256 + tid] = r;

    // ---- Release our half, trigger per-row MLP on second finisher
    __threadfence();
    __syncthreads();
    if (tid == 0) {
        int old = atomicAdd(&g_row_done[row], 1);
        s_do_mlp = (old == 1);
        if (old == 1) g_row_done[row] = 0;   // reset for next graph replay
    }
    __syncthreads();

    if (s_do_mlp) {
        // fc1: thread t -> h = t>>3 (0..31), slice = t&7 (16 float4 strided)
        int h = tid >> 3, sl = tid & 7;
        const float4* xr = (const float4*)(g_x + (size_t)row * 512);
        const float4* wr = (const float4*)(fc1_w) + h * 128;
        float p = 0.f;
#pragma unroll
        for (int k = 0; k < 16; k++) {
            int j4 = sl + 8 * k;
            float4 w = __ldg(&wr[j4]);
            float4 x = ld_cg_f4(&xr[j4]);   // L2-coherent (other block's half)
            p = fmaf(w.x, x.x, p); p = fmaf(w.y, x.y, p);
            p = fmaf(w.z, x.z, p); p = fmaf(w.w, x.w, p);
        }
        p += __shfl_xor_sync(0xffffffffu, p, 1);
        p += __shfl_xor_sync(0xffffffffu, p, 2);
        p += __shfl_xor_sync(0xffffffffu, p, 4);
        if (sl == 0)
            s_y1[h] = fminf(fmaxf(p + __ldg(&fc1_b[h]), 0.f), 1.f);
        __syncthreads();

        if (tid < 32) {
            float y2 = __ldg(&fc2_b[tid]);
#pragma unroll
            for (int j = 0; j < 32; j++)
                y2 = fmaf(__ldg(&fc2_w[tid * 32 + j]), s_y1[j], y2);
            y2 = fminf(fmaxf(y2, 0.f), 1.f);
            float p3 = __ldg(&fc3_w[tid]) * y2;
#pragma unroll
            for (int o = 16; o; o >>= 1) p3 += __shfl_xor_sync(0xffffffffu, p3, o);
            if (tid == 0) out[row] = p3 + __ldg(&fc3_b[0]);
        }
    }

    // ---- Reset shared counters (last block)
    __syncthreads();
    if (tid == 0) {
        int f = atomicAdd(&g_fin, 1);
        if (f == 2 * BATCH - 1) {
            g_claim = 0; g_done = 0; g_fin = 0;
            __threadfence();
        }
    }
}

// ---------------------------------------------------------------------------
extern "C" void kernel_launch(void* const* d_in, const int* in_sizes, int n_in,
                              void* d_out, int out_size) {
    const float* wf    = (const float*)d_in[0];
    const float* bf    = (const float*)d_in[1];
    const float* ft_w  = (const float*)d_in[2];
    const float* ft_b  = (const float*)d_in[3];
    const float* fc1_w = (const float*)d_in[4];
    const float* fc1_b = (const float*)d_in[5];
    const float* fc2_w = (const float*)d_in[6];
    const float* fc2_b = (const float*)d_in[7];
    const float* fc3_w = (const float*)d_in[8];
    const float* fc3_b = (const float*)d_in[9];
    float* out = (float*)d_out;

    ft_kernel<<<2 * BATCH, 256>>>(wf, bf, ft_w, ft_b,
                                  fc1_w, fc1_b, fc2_w, fc2_b, fc3_w, fc3_b, out);
}